// round 12
// baseline (speedup 1.0000x reference)
#include <cuda_runtime.h>

typedef unsigned int u32;
#define HD __host__ __device__

#define OUT_B 10240000u   // band stride (50*50*4096)
#define OUT_T 204800u     // t stride   (50*4096)

// ============ constexpr double math (compile-time filter design) ============
struct CD { double re, im; };
HD constexpr CD cadd(CD a, CD b){ return {a.re+b.re, a.im+b.im}; }
HD constexpr CD csub(CD a, CD b){ return {a.re-b.re, a.im-b.im}; }
HD constexpr CD cmul(CD a, CD b){ return {a.re*b.re - a.im*b.im, a.re*b.im + a.im*b.re}; }
HD constexpr CD cdiv(CD a, CD b){ double d = b.re*b.re + b.im*b.im;
    return {(a.re*b.re + a.im*b.im)/d, (a.im*b.re - a.re*b.im)/d}; }
HD constexpr double d_sqrt(double x){ double y = x > 1.0 ? x : 1.0;
    for (int i = 0; i < 80; i++) y = 0.5*(y + x/y); return y; }
HD constexpr CD c_sqrt(CD z){ double r = d_sqrt(z.re*z.re + z.im*z.im);
    double u = d_sqrt((r + z.re)*0.5); double v = d_sqrt((r - z.re)*0.5);
    if (z.im < 0.0) v = -v; return {u, v}; }
HD constexpr double d_sin(double x){ double t = x, s = x, x2 = x*x;
    for (int k = 1; k <= 14; k++){ t *= -x2/((2.0*k)*(2.0*k+1.0)); s += t; } return s; }
HD constexpr double d_cos(double x){ double t = 1.0, s = 1.0, x2 = x*x;
    for (int k = 1; k <= 14; k++){ t *= -x2/((2.0*k-1.0)*(2.0*k)); s += t; } return s; }
HD constexpr double d_tan(double x){ return d_sin(x)/d_cos(x); }

// scipy-equivalent butter(2) bandpass + sosfilt_zi, fs=2 (b1=0, b2=-b0 per section)
struct Sos { double b0[2], a1[2], a2[2], zi0[2], zi1[2]; };
HD constexpr Sos design(double w1, double w2){
    const double PI = 3.141592653589793238462643383279502884;
    double warped0 = 4.0 * d_tan(PI * w1 * 0.5);
    double warped1 = 4.0 * d_tan(PI * w2 * 0.5);
    double bw = warped1 - warped0;
    double wo = d_sqrt(warped0 * warped1);
    double s = d_sqrt(0.5);
    CD plp[2] = { {-s*bw*0.5, -s*bw*0.5}, { s*bw*0.5, -s*bw*0.5} };
    CD disc[2] = { c_sqrt(csub(cmul(plp[0],plp[0]), CD{wo*wo, 0.0})),
                   c_sqrt(csub(cmul(plp[1],plp[1]), CD{wo*wo, 0.0})) };
    CD pbp[4] = { cadd(plp[0],disc[0]), cadd(plp[1],disc[1]),
                  csub(plp[0],disc[0]), csub(plp[1],disc[1]) };
    CD prod = {1.0, 0.0};
    for (int i = 0; i < 4; i++) prod = cmul(prod, csub(CD{4.0,0.0}, pbp[i]));
    double gain = bw*bw*16.0 / prod.re;
    CD pos[2] = {}; int np = 0;
    for (int i = 0; i < 4; i++){
        CD pd = cdiv(cadd(CD{4.0,0.0}, pbp[i]), csub(CD{4.0,0.0}, pbp[i]));
        if (pd.im > 0.0 && np < 2){ pos[np] = pd; np++; }
    }
    Sos S{};
    S.b0[0] = gain; S.b0[1] = 1.0;
    for (int i = 0; i < 2; i++){
        S.a1[i] = -2.0*pos[i].re;
        S.a2[i] = pos[i].re*pos[i].re + pos[i].im*pos[i].im;
    }
    double scale = 1.0;
    for (int sI = 0; sI < 2; sI++){
        double b0 = S.b0[sI], b2 = -S.b0[sI], a1 = S.a1[sI], a2 = S.a2[sI];
        double B0 = -a1*b0, B1 = b2 - a2*b0, det = 1.0 + a1 + a2;
        S.zi0[sI] = scale * (B0 + B1) / det;
        S.zi1[sI] = scale * ((1.0 + a1)*B1 - a2*B0) / det;
        scale *= (b0 + b2) / (1.0 + a1 + a2);
    }
    return S;
}

// L[t][i]: full filtfilt (odd-ext 49, fwd, rev, bwd, rev, slice, demean over t)
// applied to basis vector e_i, double precision, then cast to float.
struct LM { float m[50][50]; };
HD constexpr LM build_lm(int band){
    Sos S = band ? design(0.20, 0.40) : design(0.05, 0.15);
    LM r{};
    for (int i = 0; i < 50; i++){
        double e[148] = {};
        for (int k = 0; k < 49; k++)  e[k]      = 2.0*(i==0)  - (double)((49-k)==i);
        for (int j = 0; j < 50; j++)  e[49+j]   = (double)(j==i);
        for (int j = 0; j < 49; j++)  e[99+j]   = 2.0*(i==49) - (double)((48-j)==i);
        for (int pass = 0; pass < 2; pass++){
            double e0 = e[0];
            double z00 = S.zi0[0]*e0, z01 = S.zi1[0]*e0;
            double z10 = S.zi0[1]*e0, z11 = S.zi1[1]*e0;
            for (int k = 0; k < 148; k++){
                double v  = e[k];
                double y0 = S.b0[0]*v  + z00; z00 = z01 - S.a1[0]*y0; z01 = -S.b0[0]*v  - S.a2[0]*y0;
                double y1 = S.b0[1]*y0 + z10; z10 = z11 - S.a1[1]*y1; z11 = -S.b0[1]*y0 - S.a2[1]*y1;
                e[k] = y1;
            }
            for (int k = 0; k < 74; k++){ double t = e[k]; e[k] = e[147-k]; e[147-k] = t; }
        }
        double mean = 0.0;
        for (int t = 0; t < 50; t++) mean += e[49+t];
        mean *= 0.02;
        for (int t = 0; t < 50; t++) r.m[t][i] = (float)(e[49+t] - mean);
    }
    return r;
}

// ============ fused kernel ============
// CTA = (c-tile of 32) x (all 50 b) x (both bands); 640 threads = 20 warps.
// 100 (band,b) row-tasks, 5 per warp, perfectly balanced; lane = c within tile.
// Pass 1: y = L x (FFMA-imm dots), store unscaled y, 1/s -> smem.
// Pass 2: rescale own values with is_sm[band][t][lane] (cross-channel b'=t broadcast).
template<int B>
__device__ __forceinline__ void proc(const float xr[50], float* ob, int b, int lane,
                                     float (&is_sm)[2][50][32])
{
    constexpr LM lf = build_lm(B);   // compile-time; coefficients fold to FFMA immediates
    float sq = 0.f;
#pragma unroll
    for (int t = 0; t < 50; t++){
        float a0 = 0.f, a1 = 0.f, a2 = 0.f, a3 = 0.f;
#pragma unroll
        for (int s = 0; s < 48; s += 4){
            a0 = fmaf(xr[s+0], lf.m[t][s+0], a0);
            a1 = fmaf(xr[s+1], lf.m[t][s+1], a1);
            a2 = fmaf(xr[s+2], lf.m[t][s+2], a2);
            a3 = fmaf(xr[s+3], lf.m[t][s+3], a3);
        }
        a0 = fmaf(xr[48], lf.m[t][48], a0);
        a1 = fmaf(xr[49], lf.m[t][49], a1);
        float y = (a0 + a1) + (a2 + a3);
        sq = fmaf(y, y, sq);
        ob[(u32)t * OUT_T] = y;
    }
    is_sm[B][b][lane] = rsqrtf(sq * (1.0f / 49.0f));
}

__global__ void __launch_bounds__(640, 1)
fused_kernel(const float* __restrict__ xg, float* __restrict__ out)
{
    __shared__ float is_sm[2][50][32];
    const int lane = threadIdx.x & 31;
    const int w    = threadIdx.x >> 5;                // 0..19
    const u32 c    = blockIdx.x * 32u + (u32)lane;

    // ---- pass 1: dots + unscaled store + 1/s ----
#pragma unroll 1
    for (int k = 0; k < 5; k++){
        const int task = w + 20 * k;                  // 0..99
        const int band = (task >= 50);
        const int b    = band ? task - 50 : task;
        const u32 ch   = (u32)b * 4096u + c;

        const float* xb = xg + ch;
        float xr[50];
#pragma unroll
        for (int s = 0; s < 50; s++) xr[s] = __ldg(xb + (u32)s * OUT_T);

        float* ob = out + (u32)band * OUT_B + ch;
        if (band == 0) proc<0>(xr, ob, b, lane, is_sm);
        else           proc<1>(xr, ob, b, lane, is_sm);
    }
    __syncthreads();

    // ---- pass 2: out[band,t,b,c] *= 1/s[band][channel (b'=t, c)] ----
    // (reference's _tensor_zscore broadcasts m[:,None,:]/s[:,None,:] ([B,1,C])
    //  against [T,B,C] with T==B; residual mean of demeaned y is ~0, dropped)
#pragma unroll 1
    for (int k = 0; k < 5; k++){
        const int task = w + 20 * k;
        const int band = (task >= 50);
        const int b    = band ? task - 50 : task;
        float* ob = out + (u32)band * OUT_B + (u32)b * 4096u + c;
#pragma unroll
        for (int t = 0; t < 50; t++)
            ob[(u32)t * OUT_T] *= is_sm[band][t][lane];
    }
}

extern "C" void kernel_launch(void* const* d_in, const int* in_sizes, int n_in,
                              void* d_out, int out_size)
{
    (void)in_sizes; (void)n_in; (void)out_size;
    fused_kernel<<<128, 640>>>((const float*)d_in[0], (float*)d_out);
}

// round 13
// speedup vs baseline: 1.2607x; 1.2607x over previous
#include <cuda_runtime.h>

typedef unsigned int u32;
#define HD __host__ __device__

#define OUT_B 10240000u   // band stride (50*50*4096)
#define OUT_T 204800u     // t stride   (50*4096)

// per-channel 1/s: [band][b*4096+c]
__device__ __align__(16) float g_is[2][204800];

// ============ constexpr double math (compile-time filter design) ============
struct CD { double re, im; };
HD constexpr CD cadd(CD a, CD b){ return {a.re+b.re, a.im+b.im}; }
HD constexpr CD csub(CD a, CD b){ return {a.re-b.re, a.im-b.im}; }
HD constexpr CD cmul(CD a, CD b){ return {a.re*b.re - a.im*b.im, a.re*b.im + a.im*b.re}; }
HD constexpr CD cdiv(CD a, CD b){ double d = b.re*b.re + b.im*b.im;
    return {(a.re*b.re + a.im*b.im)/d, (a.im*b.re - a.re*b.im)/d}; }
HD constexpr double d_sqrt(double x){ double y = x > 1.0 ? x : 1.0;
    for (int i = 0; i < 80; i++) y = 0.5*(y + x/y); return y; }
HD constexpr CD c_sqrt(CD z){ double r = d_sqrt(z.re*z.re + z.im*z.im);
    double u = d_sqrt((r + z.re)*0.5); double v = d_sqrt((r - z.re)*0.5);
    if (z.im < 0.0) v = -v; return {u, v}; }
HD constexpr double d_sin(double x){ double t = x, s = x, x2 = x*x;
    for (int k = 1; k <= 14; k++){ t *= -x2/((2.0*k)*(2.0*k+1.0)); s += t; } return s; }
HD constexpr double d_cos(double x){ double t = 1.0, s = 1.0, x2 = x*x;
    for (int k = 1; k <= 14; k++){ t *= -x2/((2.0*k-1.0)*(2.0*k)); s += t; } return s; }
HD constexpr double d_tan(double x){ return d_sin(x)/d_cos(x); }

// scipy-equivalent butter(2) bandpass + sosfilt_zi, fs=2 (b1=0, b2=-b0 per section)
struct Sos { double b0[2], a1[2], a2[2], zi0[2], zi1[2]; };
HD constexpr Sos design(double w1, double w2){
    const double PI = 3.141592653589793238462643383279502884;
    double warped0 = 4.0 * d_tan(PI * w1 * 0.5);
    double warped1 = 4.0 * d_tan(PI * w2 * 0.5);
    double bw = warped1 - warped0;
    double wo = d_sqrt(warped0 * warped1);
    double s = d_sqrt(0.5);
    CD plp[2] = { {-s*bw*0.5, -s*bw*0.5}, { s*bw*0.5, -s*bw*0.5} };
    CD disc[2] = { c_sqrt(csub(cmul(plp[0],plp[0]), CD{wo*wo, 0.0})),
                   c_sqrt(csub(cmul(plp[1],plp[1]), CD{wo*wo, 0.0})) };
    CD pbp[4] = { cadd(plp[0],disc[0]), cadd(plp[1],disc[1]),
                  csub(plp[0],disc[0]), csub(plp[1],disc[1]) };
    CD prod = {1.0, 0.0};
    for (int i = 0; i < 4; i++) prod = cmul(prod, csub(CD{4.0,0.0}, pbp[i]));
    double gain = bw*bw*16.0 / prod.re;
    CD pos[2] = {}; int np = 0;
    for (int i = 0; i < 4; i++){
        CD pd = cdiv(cadd(CD{4.0,0.0}, pbp[i]), csub(CD{4.0,0.0}, pbp[i]));
        if (pd.im > 0.0 && np < 2){ pos[np] = pd; np++; }
    }
    Sos S{};
    S.b0[0] = gain; S.b0[1] = 1.0;
    for (int i = 0; i < 2; i++){
        S.a1[i] = -2.0*pos[i].re;
        S.a2[i] = pos[i].re*pos[i].re + pos[i].im*pos[i].im;
    }
    double scale = 1.0;
    for (int sI = 0; sI < 2; sI++){
        double b0 = S.b0[sI], b2 = -S.b0[sI], a1 = S.a1[sI], a2 = S.a2[sI];
        double B0 = -a1*b0, B1 = b2 - a2*b0, det = 1.0 + a1 + a2;
        S.zi0[sI] = scale * (B0 + B1) / det;
        S.zi1[sI] = scale * ((1.0 + a1)*B1 - a2*B0) / det;
        scale *= (b0 + b2) / (1.0 + a1 + a2);
    }
    return S;
}

// L[t][i]: full filtfilt (odd-ext 49, fwd, rev, bwd, rev, slice, demean over t)
// applied to basis vector e_i, double precision, then cast to float.
struct LM { float m[50][50]; };
HD constexpr LM build_lm(int band){
    Sos S = band ? design(0.20, 0.40) : design(0.05, 0.15);
    LM r{};
    for (int i = 0; i < 50; i++){
        double e[148] = {};
        for (int k = 0; k < 49; k++)  e[k]      = 2.0*(i==0)  - (double)((49-k)==i);
        for (int j = 0; j < 50; j++)  e[49+j]   = (double)(j==i);
        for (int j = 0; j < 49; j++)  e[99+j]   = 2.0*(i==49) - (double)((48-j)==i);
        for (int pass = 0; pass < 2; pass++){
            double e0 = e[0];
            double z00 = S.zi0[0]*e0, z01 = S.zi1[0]*e0;
            double z10 = S.zi0[1]*e0, z11 = S.zi1[1]*e0;
            for (int k = 0; k < 148; k++){
                double v  = e[k];
                double y0 = S.b0[0]*v  + z00; z00 = z01 - S.a1[0]*y0; z01 = -S.b0[0]*v  - S.a2[0]*y0;
                double y1 = S.b0[1]*y0 + z10; z10 = z11 - S.a1[1]*y1; z11 = -S.b0[1]*y0 - S.a2[1]*y1;
                e[k] = y1;
            }
            for (int k = 0; k < 74; k++){ double t = e[k]; e[k] = e[147-k]; e[147-k] = t; }
        }
        double mean = 0.0;
        for (int t = 0; t < 50; t++) mean += e[49+t];
        mean *= 0.02;
        for (int t = 0; t < 50; t++) r.m[t][i] = (float)(e[49+t] - mean);
    }
    return r;
}

// ============ kernel 1: y = L x (FFMA-imm GEMM) + 1/s  [byte-identical to R9] ============
template<int B>
__device__ __forceinline__ void proc(const float xr[50], float* ob, u32 ch)
{
    constexpr LM lf = build_lm(B);   // compile-time; coefficients fold to FFMA immediates
    float sq = 0.f;
#pragma unroll
    for (int t = 0; t < 50; t++){
        float a0 = 0.f, a1 = 0.f, a2 = 0.f, a3 = 0.f;
#pragma unroll
        for (int s = 0; s < 48; s += 4){
            a0 = fmaf(xr[s+0], lf.m[t][s+0], a0);
            a1 = fmaf(xr[s+1], lf.m[t][s+1], a1);
            a2 = fmaf(xr[s+2], lf.m[t][s+2], a2);
            a3 = fmaf(xr[s+3], lf.m[t][s+3], a3);
        }
        a0 = fmaf(xr[48], lf.m[t][48], a0);
        a1 = fmaf(xr[49], lf.m[t][49], a1);
        float y = (a0 + a1) + (a2 + a3);
        sq = fmaf(y, y, sq);
        ob[(u32)B * OUT_B + (u32)t * OUT_T] = y;
    }
    g_is[B][ch] = rsqrtf(sq * (1.0f / 49.0f));
}

__global__ void __launch_bounds__(256, 2)
gemm_kernel(const float* __restrict__ xg, float* __restrict__ out)
{
    const int lane = threadIdx.x & 31;
    const int w    = threadIdx.x >> 5;
    const u32 gw   = blockIdx.x * 8u + (u32)w;   // 0..6399 : warp = one (b, c-tile)
    const u32 b    = gw >> 7;                    // 0..49
    const u32 ct   = gw & 127u;                  // 0..127
    const u32 c    = ct * 32u + (u32)lane;
    const u32 ch   = b * 4096u + c;

    const float* xb = xg + ch;
    float xr[50];
#pragma unroll
    for (int s = 0; s < 50; s++) xr[s] = __ldg(xb + (u32)s * OUT_T);

    float* ob = out + ch;
    proc<0>(xr, ob, ch);
    proc<1>(xr, ob, ch);
}

// ============ kernel 2: out[band,t,b,c] *= 1/s[band][channel (b'=t, c)] ============
// s depends only on (band, t, c) — NOT on b. Each thread owns one (band, t, c-float4)
// and RMWs 5 different b rows (16 KB apart): one scale load, MLP=5 independent RMWs.
// (reference's _tensor_zscore broadcasts m[:,None,:]/s[:,None,:] ([B,1,C]) against
//  [T,B,C] with T==B; residual mean of already-demeaned y is ~0 and is dropped)
__global__ void __launch_bounds__(256)
scaleb_kernel(float4* __restrict__ out)
{
    const u32 p    = blockIdx.x * 256u + threadIdx.x;   // 1,024,000 threads
    const u32 cf   = p & 1023u;                         // c-float4 index (0..1023)
    const u32 q    = p >> 10;                           // (band*50 + t)*10 + bq
    const u32 bq   = q % 10u;                           // b-quintet 0..9
    const u32 r    = q / 10u;
    const u32 t    = r % 50u;
    const u32 band = r / 50u;

    const float4 s = *reinterpret_cast<const float4*>(&g_is[band][t * 4096u + cf * 4u]);

    // float4 base index of (band, t, b = bq*5, c = cf*4)
    float4* o = out + (band * OUT_B + t * OUT_T) / 4u + bq * 5u * 1024u + cf;

    float4 v0 = o[0];
    float4 v1 = o[1024];
    float4 v2 = o[2048];
    float4 v3 = o[3072];
    float4 v4 = o[4096];
    v0.x *= s.x; v0.y *= s.y; v0.z *= s.z; v0.w *= s.w;
    v1.x *= s.x; v1.y *= s.y; v1.z *= s.z; v1.w *= s.w;
    v2.x *= s.x; v2.y *= s.y; v2.z *= s.z; v2.w *= s.w;
    v3.x *= s.x; v3.y *= s.y; v3.z *= s.z; v3.w *= s.w;
    v4.x *= s.x; v4.y *= s.y; v4.z *= s.z; v4.w *= s.w;
    o[0]    = v0;
    o[1024] = v1;
    o[2048] = v2;
    o[3072] = v3;
    o[4096] = v4;
}

extern "C" void kernel_launch(void* const* d_in, const int* in_sizes, int n_in,
                              void* d_out, int out_size)
{
    (void)in_sizes; (void)n_in; (void)out_size;
    gemm_kernel<<<800, 256>>>((const float*)d_in[0], (float*)d_out);
    scaleb_kernel<<<4000, 256>>>((float4*)d_out);   // 2*50*10*1024 threads
}